// round 16
// baseline (speedup 1.0000x reference)
#include <cuda_runtime.h>
#include <cuda_pipeline.h>
#include <math.h>
#include <stdint.h>

#define B_   16
#define C_   384
#define CH_  64
#define CF_  193
#define KP_  256     // padded K dim for irfft tables
#define HW_  16384   // 128*128
#define POOLB (B_ * C_)   // 6144
#define SIDEB 104         // 12 weights + 84 tables + 8 Ws prefetch (run FIRST)
#define CLS  8            // cluster size (blocks per batch)

// dynamic smem layout (float offsets)
#define SW1_OFF 0
#define SW2_OFF 9600
#define SC_OFF  19200
#define SS_OFF  28800
#define Y0_OFF  38400
#define YS_OFF  38784
#define SRE_OFF 39168
#define SIM_OFF 39424
#define HS_OFF  39680
#define SMEM_FLOATS 39744
#define SMEM_BYTES  (SMEM_FLOATS * 4)

__device__ float g_y0[B_ * C_];          // pooled means
__device__ float g_W1c [CH_ * C_];       // W1 center taps   [j][n]
__device__ float g_W2cT[CH_ * C_];       // W2 center taps^T [j][c]
__device__ float g_dftSC[CF_ * C_];      // fwd DFT cos [k][n]
__device__ float g_dftSS[CF_ * C_];      // fwd DFT sin [k][n]
__device__ float g_dftIC[C_ * KP_];      // irfft cos*wgt [n][k], 0-padded
__device__ float g_dftIS[C_ * KP_];      // irfft sin*wgt [n][k], 0-padded
__device__ float g_sink[16];             // prefetch sink (never read)

// store one float into the smem of cluster block `rank` at local address
__device__ __forceinline__ void dsmem_st(unsigned int laddr, int rank, float v) {
    unsigned int raddr;
    asm volatile("mapa.shared::cluster.u32 %0, %1, %2;"
                 : "=r"(raddr) : "r"(laddr), "r"(rank));
    asm volatile("st.shared::cluster.f32 [%0], %1;"
                 :: "r"(raddr), "f"(v) : "memory");
}

// ---------------------------------------------------------------------------
// Kernel 1: side blocks FIRST (0..103: weights, tables, Ws prefetch — they
// fill compute idle in wave 1 of the DRAM-bound pool), then 6144 pool blocks.
// ---------------------------------------------------------------------------
__global__ __launch_bounds__(256) void pool_kernel(
    const float* __restrict__ x,
    const float* __restrict__ W1, const float* __restrict__ W2,
    const float* __restrict__ Ws1, const float* __restrict__ Ws2)
{
    const int bid = blockIdx.x;
    const int t   = threadIdx.x;

    if (bid < SIDEB) {
        const int s = bid;                              // 0..103
        if (s < 6) {
            for (int e = s * 4096 + t; e < (s + 1) * 4096; e += 256) {
                int j = e / C_, n = e - j * C_;
                g_W1c[e] = W1[j * (C_ * 9) + n * 9 + 4];
            }
        } else if (s < 12) {
            for (int e = (s - 6) * 4096 + t; e < (s - 5) * 4096; e += 256) {
                int j = e / C_, c = e - j * C_;
                g_W2cT[e] = W2[c * (CH_ * 9) + j * 9 + 4];
            }
        } else if (s < 96) {
            __shared__ float cT[C_], sT[C_];
            for (int m = t; m < C_; m += 256) {
                float sv, cv;
                sincosf((float)m * (6.283185307179586f / (float)C_), &sv, &cv);
                cT[m] = cv;
                sT[m] = sv;
            }
            __syncthreads();
            if (s < 54) {                               // forward [k][n]
                const int g = s - 12;
                const int NT = CF_ * C_;
                const int lo = (NT * g) / 42, hi = (NT * (g + 1)) / 42;
                for (int e = lo + t; e < hi; e += 256) {
                    int k = e / C_, n = e - k * C_;
                    int m = (k * n) % C_;
                    g_dftSC[e] = cT[m];
                    g_dftSS[e] = sT[m];
                }
            } else {                                    // inverse [n][KP]
                const int g = s - 54;
                const int NT = C_ * KP_;
                const int lo = (NT * g) / 42, hi = (NT * (g + 1)) / 42;
                for (int e = lo + t; e < hi; e += 256) {
                    int n = e / KP_, k = e - n * KP_;
                    if (k >= CF_) { g_dftIC[e] = 0.f; g_dftIS[e] = 0.f; continue; }
                    int m = (k * n) % C_;
                    float wgt = (k >= 1 && k <= 191) ? 2.f : 1.f;
                    g_dftIC[e] = wgt * cT[m];
                    g_dftIS[e] = wgt * sT[m];
                }
            }
        } else {                                        // Ws1/Ws2 L2 prefetch
            const int g = s - 96;                       // 0..7
            const float* src = (g < 4) ? Ws1 : Ws2;
            const int NT = CF_ * C_;
            const int gg = g & 3;
            const int lo = (NT * gg) / 4, hi = (NT * (gg + 1)) / 4;
            float acc = 0.f;
            for (int e = lo + t; e < hi; e += 256) acc += __ldcg(src + e);
#pragma unroll
            for (int o = 16; o > 0; o >>= 1) acc += __shfl_down_sync(0xffffffffu, acc, o);
            if (t == 0 && acc == 1e38f) g_sink[g] = acc;   // never true; keeps loads
        }
        return;
    }

    const int bc = bid - SIDEB;
    const float4* __restrict__ p =
        reinterpret_cast<const float4*>(x + (size_t)bc * HW_);
    float s = 0.f;
#pragma unroll
    for (int i = 0; i < 16; ++i) {
        float4 v = __ldcs(p + t + 256 * i);
        s += (v.x + v.y) + (v.z + v.w);
    }
#pragma unroll
    for (int o = 16; o > 0; o >>= 1) s += __shfl_down_sync(0xffffffffu, s, o);
    __shared__ float ws[8];
    if ((t & 31) == 0) ws[t >> 5] = s;
    __syncthreads();
    if (t < 8) {
        s = ws[t];
#pragma unroll
        for (int o = 4; o > 0; o >>= 1) s += __shfl_down_sync(0xffu, s, o);
        if (t == 0) g_y0[bc] = s * (1.f / (float)HW_);
    }
}

// ---------------------------------------------------------------------------
// Kernel 2: whole tail, one launch. 16 clusters of 8 blocks (128 x 512).
// Phase 0 cp.async-stages this rank's Ws1/Ws2/dftSC/dftSS rows into smem
// (overlaps the gate chain); spec is all-smem; bins pushed via DSMEM;
// cluster barrier orders them; irfft from global [n][KP] tables.
// ---------------------------------------------------------------------------
__global__ __launch_bounds__(512) __cluster_dims__(CLS, 1, 1)
void k_tail(
    const float* __restrict__ b1, const float* __restrict__ b2,
    const float* __restrict__ Ws1, const float* __restrict__ bs1,
    const float* __restrict__ Ws2, const float* __restrict__ bs2,
    float* __restrict__ out)
{
    extern __shared__ float sm[];
    float* sW1 = sm + SW1_OFF;
    float* sW2 = sm + SW2_OFF;
    float* sC  = sm + SC_OFF;
    float* sS  = sm + SS_OFF;
    float* y0s = sm + Y0_OFF;
    float* ys  = sm + YS_OFF;
    float* sRe = sm + SRE_OFF;
    float* sIm = sm + SIM_OFF;
    float* hs  = sm + HS_OFF;

    const int b    = blockIdx.x / CLS;
    const int rank = blockIdx.x - b * CLS;     // 0..7 == cluster rank
    const int t    = threadIdx.x;              // 0..511
    const int w    = t >> 5;                   // 0..15
    const int lane = t & 31;

    const int base = rank * 25;
    const int cnt  = (base + 25 <= CF_) ? 25 : (CF_ - base);  // rank7: 18
    const int nv4  = cnt * (C_ / 4);           // float4 count per array

    // ---- phase 0: async-stage spec operands; load y0; zero pad bins ----
    {
        float4*       d1 = reinterpret_cast<float4*>(sW1);
        float4*       d2 = reinterpret_cast<float4*>(sW2);
        float4*       dc = reinterpret_cast<float4*>(sC);
        float4*       ds = reinterpret_cast<float4*>(sS);
        const float4* s1 = reinterpret_cast<const float4*>(Ws1 + base * C_);
        const float4* s2 = reinterpret_cast<const float4*>(Ws2 + base * C_);
        const float4* sc = reinterpret_cast<const float4*>(g_dftSC + base * C_);
        const float4* ss = reinterpret_cast<const float4*>(g_dftSS + base * C_);
        for (int e = t; e < nv4; e += 512) {
            __pipeline_memcpy_async(&d1[e], &s1[e], 16);
            __pipeline_memcpy_async(&d2[e], &s2[e], 16);
            __pipeline_memcpy_async(&dc[e], &sc[e], 16);
            __pipeline_memcpy_async(&ds[e], &ss[e], 16);
        }
        __pipeline_commit();
    }
    if (t < C_) y0s[t] = g_y0[b * C_ + t];
    if (t >= CF_ && t < KP_) { sRe[t] = 0.f; sIm[t] = 0.f; }
    __syncthreads();

    // ---- phase 1a: h[j], warp per j (4 rounds) ----
    const float4* __restrict__ y04 = reinterpret_cast<const float4*>(y0s);
#pragma unroll
    for (int r = 0; r < 4; ++r) {
        const int j = w + 16 * r;
        const float4* __restrict__ wr = reinterpret_cast<const float4*>(g_W1c + j * C_);
        float acc = 0.f;
#pragma unroll
        for (int i = 0; i < 3; ++i) {
            float4 a = y04[lane * 3 + i];
            float4 ww = wr[lane * 3 + i];
            acc += a.x * ww.x + a.y * ww.y + a.z * ww.z + a.w * ww.w;
        }
#pragma unroll
        for (int o = 16; o > 0; o >>= 1) acc += __shfl_down_sync(0xffffffffu, acc, o);
        if (lane == 0) hs[j] = fmaxf(acc + b1[j], 0.f);
    }
    __syncthreads();

    // ---- phase 1b: y[c], thread per c ----
    if (t < C_) {
        float acc = b2[t];
#pragma unroll
        for (int j = 0; j < CH_; ++j)
            acc += hs[j] * g_W2cT[j * C_ + t];
        ys[t] = 1.f / (1.f + expf(-acc));
    }
    __pipeline_wait_prior(0);
    __syncthreads();

    // ---- phase 2: bins, warp per bin; ALL-smem operands; DSMEM push ----
    {
        const float4* __restrict__ yv4 = reinterpret_cast<const float4*>(ys);
        for (int kk = w; kk < cnt; kk += 16) {
            const int k = base + kk;
            const float4* __restrict__ tc = reinterpret_cast<const float4*>(sC + kk * C_);
            const float4* __restrict__ tn = reinterpret_cast<const float4*>(sS + kk * C_);
            const float4* __restrict__ u4 = reinterpret_cast<const float4*>(sW1 + kk * C_);
            const float4* __restrict__ v4 = reinterpret_cast<const float4*>(sW2 + kk * C_);
            float re = 0.f, im = 0.f, a1 = 0.f, a2 = 0.f;
#pragma unroll
            for (int i = 0; i < 3; ++i) {
                const int q = lane * 3 + i;
                float4 y = yv4[q];
                float4 c = tc[q], sn = tn[q], u = u4[q], v = v4[q];
                re += y.x * c.x + y.y * c.y + y.z * c.z + y.w * c.w;
                im -= y.x * sn.x + y.y * sn.y + y.z * sn.z + y.w * sn.w;
                a1 += y.x * u.x + y.y * u.y + y.z * u.z + y.w * u.w;
                a2 += y.x * v.x + y.y * v.y + y.z * v.z + y.w * v.w;
            }
#pragma unroll
            for (int o = 16; o > 0; o >>= 1) {
                re += __shfl_down_sync(0xffffffffu, re, o);
                im += __shfl_down_sync(0xffffffffu, im, o);
                a1 += __shfl_down_sync(0xffffffffu, a1, o);
                a2 += __shfl_down_sync(0xffffffffu, a2, o);
            }
            if (lane == 0) {
                float s1  = fmaxf(a1 + bs1[k], 0.f);
                float s2  = fmaxf(a2 + bs2[k], 0.f);
                float amp = sqrtf(re * re + im * im) * s1;
                float ph  = atan2f(im, re) * s2;
                float sp, cp;
                sincosf(ph, &sp, &cp);
                const float vRe = amp * cp;
                const float vIm = amp * sp;
                const unsigned int aRe =
                    (unsigned int)__cvta_generic_to_shared(&sRe[k]);
                const unsigned int aIm =
                    (unsigned int)__cvta_generic_to_shared(&sIm[k]);
#pragma unroll
                for (int rr = 0; rr < CLS; ++rr) {
                    dsmem_st(aRe, rr, vRe);
                    dsmem_st(aIm, rr, vIm);
                }
            }
        }
    }

    // cluster barrier: arrive(release) / wait(acquire) orders DSMEM stores
    asm volatile("barrier.cluster.arrive.aligned;" ::: "memory");
    asm volatile("barrier.cluster.wait.aligned;" ::: "memory");

    // ---- phase 3: irfft outputs [48*rank, 48*rank+48), warp per n ----
    const float4* __restrict__ re4 = reinterpret_cast<const float4*>(sRe);
    const float4* __restrict__ im4 = reinterpret_cast<const float4*>(sIm);
#pragma unroll
    for (int r = 0; r < 3; ++r) {
        const int n = rank * 48 + w + 16 * r;
        const float4* __restrict__ tc = reinterpret_cast<const float4*>(g_dftIC + n * KP_);
        const float4* __restrict__ tn = reinterpret_cast<const float4*>(g_dftIS + n * KP_);
        float acc = 0.f;
#pragma unroll
        for (int i = 0; i < 2; ++i) {
            const int q = lane * 2 + i;
            float4 c = tc[q], sn = tn[q], rr = re4[q], mm = im4[q];
            acc += c.x * rr.x + c.y * rr.y + c.z * rr.z + c.w * rr.w;
            acc -= sn.x * mm.x + sn.y * mm.y + sn.z * mm.z + sn.w * mm.w;
        }
#pragma unroll
        for (int o = 16; o > 0; o >>= 1) acc += __shfl_down_sync(0xffffffffu, acc, o);
        if (lane == 0) {
            float xr = acc * (1.f / (float)C_);
            out[b * C_ + n] = xr * ys[n];
        }
    }
}

// ---------------------------------------------------------------------------
extern "C" void kernel_launch(void* const* d_in, const int* in_sizes, int n_in,
                              void* d_out, int out_size) {
    const float* x   = (const float*)d_in[0];
    const float* W1  = (const float*)d_in[1];
    const float* b1  = (const float*)d_in[2];
    const float* W2  = (const float*)d_in[3];
    const float* b2  = (const float*)d_in[4];
    const float* Ws1 = (const float*)d_in[5];
    const float* bs1 = (const float*)d_in[6];
    const float* Ws2 = (const float*)d_in[7];
    const float* bs2 = (const float*)d_in[8];
    float* out = (float*)d_out;

    cudaFuncSetAttribute(k_tail, cudaFuncAttributeMaxDynamicSharedMemorySize,
                         SMEM_BYTES);

    pool_kernel<<<SIDEB + POOLB, 256>>>(x, W1, W2, Ws1, Ws2);
    k_tail<<<B_ * CLS, 512, SMEM_BYTES>>>(b1, b2, Ws1, bs1, Ws2, bs2, out);
}

// round 17
// speedup vs baseline: 1.0772x; 1.0772x over previous
#include <cuda_runtime.h>
#include <math.h>
#include <stdint.h>

#define B_   16
#define C_   384
#define CH_  64
#define CF_  193
#define KP_  256     // padded K dim for irfft tables
#define HW_  16384   // 128*128
#define POOLB (B_ * C_)   // 6144
#define SIDEB 104         // 12 weights + 84 tables + 8 Ws prefetch (run FIRST)
#define CLS  8            // cluster size (blocks per batch)

__device__ float g_y0[B_ * C_];          // pooled means
__device__ float g_W1c [CH_ * C_];       // W1 center taps   [j][n]
__device__ float g_W2cT[CH_ * C_];       // W2 center taps^T [j][c]
__device__ float g_dftSC[CF_ * C_];      // fwd DFT cos [k][n]
__device__ float g_dftSS[CF_ * C_];      // fwd DFT sin [k][n]
__device__ float g_dftIC[C_ * KP_];      // irfft cos*wgt [n][k], 0-padded
__device__ float g_dftIS[C_ * KP_];      // irfft sin*wgt [n][k], 0-padded
__device__ float g_sink[16];             // prefetch sink (never read)

// store one float into the smem of cluster block `rank` at local address
__device__ __forceinline__ void dsmem_st(unsigned int laddr, int rank, float v) {
    unsigned int raddr;
    asm volatile("mapa.shared::cluster.u32 %0, %1, %2;"
                 : "=r"(raddr) : "r"(laddr), "r"(rank));
    asm volatile("st.shared::cluster.f32 [%0], %1;"
                 :: "r"(raddr), "f"(v) : "memory");
}

// ---------------------------------------------------------------------------
// Kernel 1: side blocks FIRST (0..103: weights, tables, Ws prefetch — they
// fill compute idle in wave 1 of the DRAM-bound pool), then 6144 pool blocks.
// Measured pool cost in this layout: ~54.9us.
// ---------------------------------------------------------------------------
__global__ __launch_bounds__(256) void pool_kernel(
    const float* __restrict__ x,
    const float* __restrict__ W1, const float* __restrict__ W2,
    const float* __restrict__ Ws1, const float* __restrict__ Ws2)
{
    const int bid = blockIdx.x;
    const int t   = threadIdx.x;

    if (bid < SIDEB) {
        const int s = bid;                              // 0..103
        if (s < 6) {
            for (int e = s * 4096 + t; e < (s + 1) * 4096; e += 256) {
                int j = e / C_, n = e - j * C_;
                g_W1c[e] = W1[j * (C_ * 9) + n * 9 + 4];
            }
        } else if (s < 12) {
            for (int e = (s - 6) * 4096 + t; e < (s - 5) * 4096; e += 256) {
                int j = e / C_, c = e - j * C_;
                g_W2cT[e] = W2[c * (CH_ * 9) + j * 9 + 4];
            }
        } else if (s < 96) {
            __shared__ float cT[C_], sT[C_];
            for (int m = t; m < C_; m += 256) {
                float sv, cv;
                sincosf((float)m * (6.283185307179586f / (float)C_), &sv, &cv);
                cT[m] = cv;
                sT[m] = sv;
            }
            __syncthreads();
            if (s < 54) {                               // forward [k][n]
                const int g = s - 12;
                const int NT = CF_ * C_;
                const int lo = (NT * g) / 42, hi = (NT * (g + 1)) / 42;
                for (int e = lo + t; e < hi; e += 256) {
                    int k = e / C_, n = e - k * C_;
                    int m = (k * n) % C_;
                    g_dftSC[e] = cT[m];
                    g_dftSS[e] = sT[m];
                }
            } else {                                    // inverse [n][KP]
                const int g = s - 54;
                const int NT = C_ * KP_;
                const int lo = (NT * g) / 42, hi = (NT * (g + 1)) / 42;
                for (int e = lo + t; e < hi; e += 256) {
                    int n = e / KP_, k = e - n * KP_;
                    if (k >= CF_) { g_dftIC[e] = 0.f; g_dftIS[e] = 0.f; continue; }
                    int m = (k * n) % C_;
                    float wgt = (k >= 1 && k <= 191) ? 2.f : 1.f;
                    g_dftIC[e] = wgt * cT[m];
                    g_dftIS[e] = wgt * sT[m];
                }
            }
        } else {                                        // Ws1/Ws2 L2 prefetch
            const int g = s - 96;                       // 0..7
            const float* src = (g < 4) ? Ws1 : Ws2;
            const int NT = CF_ * C_;
            const int gg = g & 3;
            const int lo = (NT * gg) / 4, hi = (NT * (gg + 1)) / 4;
            float acc = 0.f;
            for (int e = lo + t; e < hi; e += 256) acc += __ldcg(src + e);
#pragma unroll
            for (int o = 16; o > 0; o >>= 1) acc += __shfl_down_sync(0xffffffffu, acc, o);
            if (t == 0 && acc == 1e38f) g_sink[g] = acc;   // never true; keeps loads
        }
        return;
    }

    const int bc = bid - SIDEB;
    const float4* __restrict__ p =
        reinterpret_cast<const float4*>(x + (size_t)bc * HW_);
    float s = 0.f;
#pragma unroll
    for (int i = 0; i < 16; ++i) {
        float4 v = __ldcs(p + t + 256 * i);
        s += (v.x + v.y) + (v.z + v.w);
    }
#pragma unroll
    for (int o = 16; o > 0; o >>= 1) s += __shfl_down_sync(0xffffffffu, s, o);
    __shared__ float ws[8];
    if ((t & 31) == 0) ws[t >> 5] = s;
    __syncthreads();
    if (t < 8) {
        s = ws[t];
#pragma unroll
        for (int o = 4; o > 0; o >>= 1) s += __shfl_down_sync(0xffu, s, o);
        if (t == 0) g_y0[bc] = s * (1.f / (float)HW_);
    }
}

// ---------------------------------------------------------------------------
// Kernel 2: whole tail, one launch. 16 clusters of 8 blocks (128 x 512).
// R15-proven: bins pushed into every rank's smem via DSMEM; cluster barrier
// (release/acquire) orders them; spec operands stream from L2 (prefetched).
// Measured: ~14.8us.
// ---------------------------------------------------------------------------
__global__ __launch_bounds__(512) __cluster_dims__(CLS, 1, 1)
void k_tail(
    const float* __restrict__ b1, const float* __restrict__ b2,
    const float* __restrict__ Ws1, const float* __restrict__ bs1,
    const float* __restrict__ Ws2, const float* __restrict__ bs2,
    float* __restrict__ out)
{
    const int b    = blockIdx.x / CLS;
    const int rank = blockIdx.x - b * CLS;     // 0..7 == cluster rank
    const int t    = threadIdx.x;              // 0..511
    const int w    = t >> 5;                   // 0..15
    const int lane = t & 31;

    __shared__ __align__(16) float y0s[C_];
    __shared__ __align__(16) float ys [C_];
    __shared__ __align__(16) float sRe[KP_];
    __shared__ __align__(16) float sIm[KP_];
    __shared__ float hs[CH_];

    // phase 0: load y0; zero ONLY the pad region (never written by peers)
    if (t < C_) y0s[t] = g_y0[b * C_ + t];
    if (t >= CF_ && t < KP_) { sRe[t] = 0.f; sIm[t] = 0.f; }
    __syncthreads();

    // ---- phase 1a: h[j], warp per j (4 rounds) ----
    const float4* __restrict__ y04 = reinterpret_cast<const float4*>(y0s);
#pragma unroll
    for (int r = 0; r < 4; ++r) {
        const int j = w + 16 * r;
        const float4* __restrict__ wr = reinterpret_cast<const float4*>(g_W1c + j * C_);
        float acc = 0.f;
#pragma unroll
        for (int i = 0; i < 3; ++i) {
            float4 a = y04[lane * 3 + i];
            float4 ww = wr[lane * 3 + i];
            acc += a.x * ww.x + a.y * ww.y + a.z * ww.z + a.w * ww.w;
        }
#pragma unroll
        for (int o = 16; o > 0; o >>= 1) acc += __shfl_down_sync(0xffffffffu, acc, o);
        if (lane == 0) hs[j] = fmaxf(acc + b1[j], 0.f);
    }
    __syncthreads();

    // ---- phase 1b: y[c], thread per c ----
    if (t < C_) {
        float acc = b2[t];
#pragma unroll
        for (int j = 0; j < CH_; ++j)
            acc += hs[j] * g_W2cT[j * C_ + t];
        ys[t] = 1.f / (1.f + expf(-acc));
    }
    __syncthreads();

    // ---- phase 2: bins [25*rank ..), warp per bin; DSMEM push to all ranks ----
    {
        const int base = rank * 25;
        const int cnt  = (base + 25 <= CF_) ? 25 : (CF_ - base);  // rank7: 18
        const float4* __restrict__ yv4 = reinterpret_cast<const float4*>(ys);
        for (int kk = w; kk < cnt; kk += 16) {
            const int k = base + kk;
            const float4* __restrict__ tc = reinterpret_cast<const float4*>(g_dftSC + k * C_);
            const float4* __restrict__ tn = reinterpret_cast<const float4*>(g_dftSS + k * C_);
            const float4* __restrict__ u4 = reinterpret_cast<const float4*>(Ws1 + k * C_);
            const float4* __restrict__ v4 = reinterpret_cast<const float4*>(Ws2 + k * C_);
            float re = 0.f, im = 0.f, a1 = 0.f, a2 = 0.f;
#pragma unroll
            for (int i = 0; i < 3; ++i) {
                const int q = lane * 3 + i;
                float4 y = yv4[q];
                float4 c = tc[q], sn = tn[q], u = u4[q], v = v4[q];
                re += y.x * c.x + y.y * c.y + y.z * c.z + y.w * c.w;
                im -= y.x * sn.x + y.y * sn.y + y.z * sn.z + y.w * sn.w;
                a1 += y.x * u.x + y.y * u.y + y.z * u.z + y.w * u.w;
                a2 += y.x * v.x + y.y * v.y + y.z * v.z + y.w * v.w;
            }
#pragma unroll
            for (int o = 16; o > 0; o >>= 1) {
                re += __shfl_down_sync(0xffffffffu, re, o);
                im += __shfl_down_sync(0xffffffffu, im, o);
                a1 += __shfl_down_sync(0xffffffffu, a1, o);
                a2 += __shfl_down_sync(0xffffffffu, a2, o);
            }
            if (lane == 0) {
                float s1  = fmaxf(a1 + bs1[k], 0.f);
                float s2  = fmaxf(a2 + bs2[k], 0.f);
                float amp = sqrtf(re * re + im * im) * s1;
                float ph  = atan2f(im, re) * s2;
                float sp, cp;
                sincosf(ph, &sp, &cp);
                const float vRe = amp * cp;
                const float vIm = amp * sp;
                const unsigned int aRe =
                    (unsigned int)__cvta_generic_to_shared(&sRe[k]);
                const unsigned int aIm =
                    (unsigned int)__cvta_generic_to_shared(&sIm[k]);
#pragma unroll
                for (int rr = 0; rr < CLS; ++rr) {
                    dsmem_st(aRe, rr, vRe);
                    dsmem_st(aIm, rr, vIm);
                }
            }
        }
    }

    // cluster barrier: arrive(release) / wait(acquire) orders DSMEM stores
    asm volatile("barrier.cluster.arrive.aligned;" ::: "memory");
    asm volatile("barrier.cluster.wait.aligned;" ::: "memory");

    // ---- phase 3: irfft outputs [48*rank, 48*rank+48), warp per n ----
    const float4* __restrict__ re4 = reinterpret_cast<const float4*>(sRe);
    const float4* __restrict__ im4 = reinterpret_cast<const float4*>(sIm);
#pragma unroll
    for (int r = 0; r < 3; ++r) {
        const int n = rank * 48 + w + 16 * r;
        const float4* __restrict__ tc = reinterpret_cast<const float4*>(g_dftIC + n * KP_);
        const float4* __restrict__ tn = reinterpret_cast<const float4*>(g_dftIS + n * KP_);
        float acc = 0.f;
#pragma unroll
        for (int i = 0; i < 2; ++i) {
            const int q = lane * 2 + i;
            float4 c = tc[q], sn = tn[q], rr = re4[q], mm = im4[q];
            acc += c.x * rr.x + c.y * rr.y + c.z * rr.z + c.w * rr.w;
            acc -= sn.x * mm.x + sn.y * mm.y + sn.z * mm.z + sn.w * mm.w;
        }
#pragma unroll
        for (int o = 16; o > 0; o >>= 1) acc += __shfl_down_sync(0xffffffffu, acc, o);
        if (lane == 0) {
            float xr = acc * (1.f / (float)C_);
            out[b * C_ + n] = xr * ys[n];
        }
    }
}

// ---------------------------------------------------------------------------
extern "C" void kernel_launch(void* const* d_in, const int* in_sizes, int n_in,
                              void* d_out, int out_size) {
    const float* x   = (const float*)d_in[0];
    const float* W1  = (const float*)d_in[1];
    const float* b1  = (const float*)d_in[2];
    const float* W2  = (const float*)d_in[3];
    const float* b2  = (const float*)d_in[4];
    const float* Ws1 = (const float*)d_in[5];
    const float* bs1 = (const float*)d_in[6];
    const float* Ws2 = (const float*)d_in[7];
    const float* bs2 = (const float*)d_in[8];
    float* out = (float*)d_out;

    pool_kernel<<<SIDEB + POOLB, 256>>>(x, W1, W2, Ws1, Ws2);
    k_tail<<<B_ * CLS, 512>>>(b1, b2, Ws1, bs1, Ws2, bs2, out);
}